// round 16
// baseline (speedup 1.0000x reference)
#include <cuda_runtime.h>
#include <cuda_fp16.h>
#include <cstdint>

#define B_   8
#define C_   64
#define HW_  4096
#define N_   32768
#define K_   8192
#define CHW_ (C_*HW_)
#define OUT_ELEMS (B_*C_*HW_)
#define EPS_GAP 5.0e-4f

__device__ float  g_ze[N_ * C_];
__device__ __half g_ah[N_ * C_], g_al[N_ * C_];   // fp16 splits of -2*ze
__device__ __half g_eh[K_ * C_], g_el[K_ * C_];   // fp16 splits of emb
__device__ float  g_en2[K_];
__device__ int    g_idx[N_];
__device__ int    g_refcnt;      // pairwise-refine count
__device__ int    g_refcnt2;     // full-scan refine count (expected ~0)
__device__ int    g_reftok[N_], g_pa[N_], g_pb[N_];
__device__ int    g_reflist2[N_];
__device__ float  g_losspart[256];

// ---------------------------------------------------------------------------
// PTX helpers (sm_80-era: compile cleanly for compute_103)
// ---------------------------------------------------------------------------
__device__ __forceinline__ uint32_t smem_u32(const void* p) {
    uint32_t a;
    asm("{ .reg .u64 t; cvta.to.shared.u64 t, %1; cvt.u32.u64 %0, t; }" : "=r"(a) : "l"(p));
    return a;
}
__device__ __forceinline__ void cpasync16(uint32_t s, const void* g) {
    asm volatile("cp.async.cg.shared.global [%0], [%1], 16;" :: "r"(s), "l"(g));
}
#define CP_COMMIT() asm volatile("cp.async.commit_group;" ::: "memory")
#define CP_WAIT1()  asm volatile("cp.async.wait_group 1;" ::: "memory")
#define CP_WAIT0()  asm volatile("cp.async.wait_group 0;" ::: "memory")

__device__ __forceinline__ void ldsm4(uint32_t* r, uint32_t addr) {
    asm volatile("ldmatrix.sync.aligned.m8n8.x4.shared.b16 {%0,%1,%2,%3}, [%4];"
                 : "=r"(r[0]), "=r"(r[1]), "=r"(r[2]), "=r"(r[3]) : "r"(addr));
}
__device__ __forceinline__ void mma16816(float* d, const uint32_t* a, uint32_t b0, uint32_t b1) {
    asm volatile("mma.sync.aligned.m16n8k16.row.col.f32.f16.f16.f32 "
                 "{%0,%1,%2,%3}, {%4,%5,%6,%7}, {%8,%9}, {%0,%1,%2,%3};"
                 : "+f"(d[0]), "+f"(d[1]), "+f"(d[2]), "+f"(d[3])
                 : "r"(a[0]), "r"(a[1]), "r"(a[2]), "r"(a[3]), "r"(b0), "r"(b1));
}

// ---------------------------------------------------------------------------
// Kernel 1: pre-conv + 2-way fp16 split of (-2*ze)
// ---------------------------------------------------------------------------
__global__ void k_pre(const float* __restrict__ z,
                      const float* __restrict__ w,
                      const float* __restrict__ bias) {
    __shared__ float ws[C_ * C_];
    __shared__ float bs[C_];
    int tid = threadIdx.x;
    for (int i = tid; i < C_ * C_ / 4; i += blockDim.x)
        ((float4*)ws)[i] = ((const float4*)w)[i];
    if (tid < C_) bs[tid] = bias[tid];
    __syncthreads();

    int n   = blockIdx.x * blockDim.x + tid;
    int b   = n >> 12;
    int pos = n & 4095;
    const float* zp = z + (size_t)b * CHW_ + pos;

    float zr[C_];
#pragma unroll
    for (int c = 0; c < C_; c++) zr[c] = zp[(size_t)c * HW_];

    float*  zeout = g_ze + (size_t)n * C_;
    __half* ahp   = g_ah + (size_t)n * C_;
    __half* alp   = g_al + (size_t)n * C_;

    for (int og = 0; og < C_; og += 8) {
        float zeb[8];
        __half hb[8], lb[8];
#pragma unroll
        for (int oo = 0; oo < 8; oo++) {
            int o = og + oo;
            float acc = bs[o];
#pragma unroll
            for (int c = 0; c < C_; c++) acc += ws[o * C_ + c] * zr[c];
            zeb[oo] = acc;
            float x = -2.f * acc;
            __half h = __float2half_rn(x);
            float r = x - __half2float(h);
            hb[oo] = h; lb[oo] = __float2half_rn(r);
        }
        *(uint4*)(zeout + og)     = ((uint4*)zeb)[0];
        *(uint4*)(zeout + og + 4) = ((uint4*)zeb)[1];
        *(uint4*)(ahp + og) = *(uint4*)hb;
        *(uint4*)(alp + og) = *(uint4*)lb;
    }
}

// ---------------------------------------------------------------------------
// Kernel 2: codebook 2-way fp16 split + row norms (+ counter resets)
// ---------------------------------------------------------------------------
__global__ void k_embcvt(const float* __restrict__ emb) {
    if (blockIdx.x == 0 && threadIdx.x == 0) { g_refcnt = 0; g_refcnt2 = 0; }
    int k = blockIdx.x * blockDim.x + threadIdx.x;
    const float* e = emb + (size_t)k * C_;
    __half* hp = g_eh + (size_t)k * C_;
    __half* lp = g_el + (size_t)k * C_;
    float s = 0.f;
    for (int og = 0; og < C_; og += 8) {
        float v[8];
        ((float4*)v)[0] = *(const float4*)(e + og);
        ((float4*)v)[1] = *(const float4*)(e + og + 4);
        __half hb[8], lb[8];
#pragma unroll
        for (int i = 0; i < 8; i++) {
            float x = v[i];
            s += x * x;
            __half h = __float2half_rn(x);
            hb[i] = h; lb[i] = __float2half_rn(x - __half2float(h));
        }
        *(uint4*)(hp + og) = *(uint4*)hb;
        *(uint4*)(lp + og) = *(uint4*)lb;
    }
    g_en2[k] = s;
}

// ---------------------------------------------------------------------------
// Kernel 3: HMMA argmin (fp16 splits, top-3 tracking).
// d = ah*eh + al*eh + ah*el (fp32 accum) ~ -2 z.e  (rigorous err <~1.2e-4).
// Epilogue: s = d + en2; per-token best1/2/3; gap2<EPS -> pair refine,
// gap3<EPS -> full refine.
// ---------------------------------------------------------------------------
#define NC        128
#define NCHUNK    (K_ / NC)      // 64
#define SM_AH     0
#define SM_AL     16384
#define SM_B      32768
#define BUFSTRIDE 33280          // eh 16384 + el 16384 + en2 512
#define SMEM_TC   (SM_B + 2 * BUFSTRIDE)   // 99328

__device__ __forceinline__ void load_chunk(uint32_t sb, int buf, int kc, int tid) {
    uint32_t dst = sb + SM_B + buf * BUFSTRIDE;
#pragma unroll
    for (int i = 0; i < 4; i++) {
        int f = tid + i * 256;
        int row = f >> 3, c = f & 7;
        uint32_t off = row * 128 + ((c ^ (row & 7)) * 16);
        size_t src = (size_t)(kc + row) * 128 + c * 16;
        cpasync16(dst + off,         (const char*)g_eh + src);
        cpasync16(dst + 16384 + off, (const char*)g_el + src);
    }
    if (tid < 32)
        cpasync16(dst + 32768 + tid * 16, (const char*)g_en2 + (size_t)kc * 4 + tid * 16);
}

__global__ void __launch_bounds__(256, 2) k_argmin_mma() {
    extern __shared__ char smem[];
    uint32_t sb = smem_u32(smem);
    int tid  = threadIdx.x;
    int w    = tid >> 5;
    int lane = tid & 31;
    int t0   = blockIdx.x * 128;

    // prologue: A tiles + chunk0, chunk1
#pragma unroll
    for (int i = 0; i < 4; i++) {
        int f = tid + i * 256;
        int row = f >> 3, c = f & 7;
        uint32_t off = row * 128 + ((c ^ (row & 7)) * 16);
        size_t src = (size_t)(t0 + row) * 128 + c * 16;
        cpasync16(sb + SM_AH + off, (const char*)g_ah + src);
        cpasync16(sb + SM_AL + off, (const char*)g_al + src);
    }
    load_chunk(sb, 0, 0, tid);
    CP_COMMIT();
    load_chunk(sb, 1, NC, tid);
    CP_COMMIT();

    uint32_t aH[4][4], aL[4][4];
    float b1v[2] = {3.4e38f, 3.4e38f}, b2v[2] = {3.4e38f, 3.4e38f},
          b3v[2] = {3.4e38f, 3.4e38f};
    int   i1v[2] = {0, 0}, i2v[2] = {0, 0};

    for (int c = 0; c < NCHUNK; c++) {
        if (c < NCHUNK - 1) { CP_WAIT1(); } else { CP_WAIT0(); }
        __syncthreads();
        if (c == 0) {
            int quad = lane >> 3, rin = lane & 7;
            int arow = 16 * w + (quad & 1) * 8 + rin;
#pragma unroll
            for (int kk = 0; kk < 4; kk++) {
                uint32_t cidx = kk * 2 + (quad >> 1);
                uint32_t off  = arow * 128 + (((cidx ^ rin) & 7) * 16);
                ldsm4(aH[kk], sb + SM_AH + off);
                ldsm4(aL[kk], sb + SM_AL + off);
            }
        }
        uint32_t bbase = sb + SM_B + (c & 1) * BUFSTRIDE;
        const float* en2c = (const float*)(smem + SM_B + (c & 1) * BUFSTRIDE + 32768);
        int kc = c * NC;
        int m = lane >> 3, rin = lane & 7;

#pragma unroll 2
        for (int nt = 0; nt < 16; nt++) {
            int brow = nt * 8 + rin;
            float d[4] = {0.f, 0.f, 0.f, 0.f};
#pragma unroll
            for (int g = 0; g < 2; g++) {
                uint32_t eh4[4], el4[4];
                uint32_t off = brow * 128 + ((((g * 4 + m) ^ rin) & 7) * 16);
                ldsm4(eh4, bbase + off);
                ldsm4(el4, bbase + 16384 + off);
                mma16816(d, aH[2 * g],     eh4[0], eh4[1]);
                mma16816(d, aH[2 * g + 1], eh4[2], eh4[3]);
                mma16816(d, aL[2 * g],     eh4[0], eh4[1]);
                mma16816(d, aL[2 * g + 1], eh4[2], eh4[3]);
                mma16816(d, aH[2 * g],     el4[0], el4[1]);
                mma16816(d, aH[2 * g + 1], el4[2], el4[3]);
            }
            int col0 = nt * 8 + 2 * (lane & 3);
            float e0 = en2c[col0], e1 = en2c[col0 + 1];
            float s01[2][2] = { { d[0] + e0, d[1] + e1 },
                                { d[2] + e0, d[3] + e1 } };
            int gc0 = kc + col0;
#pragma unroll
            for (int h = 0; h < 2; h++) {
#pragma unroll
                for (int jj = 0; jj < 2; jj++) {
                    float s = s01[h][jj];
                    int   gk = gc0 + jj;
                    if (s < b3v[h]) {
                        if (s < b2v[h]) {
                            b3v[h] = b2v[h];
                            if (s < b1v[h]) {
                                b2v[h] = b1v[h]; i2v[h] = i1v[h];
                                b1v[h] = s;      i1v[h] = gk;
                            } else { b2v[h] = s; i2v[h] = gk; }
                        } else b3v[h] = s;
                    }
                }
            }
        }
        __syncthreads();
        if (c + 2 < NCHUNK) { load_chunk(sb, c & 1, (c + 2) * NC, tid); CP_COMMIT(); }
    }

    // quad reduce: merge sorted top-3 triples across 4 lanes
#pragma unroll
    for (int h = 0; h < 2; h++) {
        float v1 = b1v[h], v2 = b2v[h], v3 = b3v[h];
        int   j1 = i1v[h], j2 = i2v[h];
#pragma unroll
        for (int off = 2; off > 0; off >>= 1) {
            float c1 = __shfl_down_sync(0xffffffffu, v1, off, 4);
            float c2 = __shfl_down_sync(0xffffffffu, v2, off, 4);
            float c3 = __shfl_down_sync(0xffffffffu, v3, off, 4);
            int   k1 = __shfl_down_sync(0xffffffffu, j1, off, 4);
            int   k2 = __shfl_down_sync(0xffffffffu, j2, off, 4);
            bool sw = (c1 < v1) || (c1 == v1 && k1 < j1);
            if (sw) {
                float tv; int ti;
                tv = v1; v1 = c1; c1 = tv;  ti = j1; j1 = k1; k1 = ti;
                tv = v2; v2 = c2; c2 = tv;  ti = j2; j2 = k2; k2 = ti;
                tv = v3; v3 = c3; c3 = tv;
            }
            // v1 is champion; merge remainder
            bool t2 = (c1 < v2) || (c1 == v2 && k1 < j2);
            float n3;
            if (t2) { n3 = fminf(v2, c2); v2 = c1; j2 = k1; }
            else    { n3 = fminf(v3, c1); }
            v3 = n3;
        }
        if ((lane & 3) == 0) {
            int token = t0 + w * 16 + (lane >> 2) + h * 8;
            g_idx[token] = j1;
            if (v3 - v1 < EPS_GAP) {
                int s = atomicAdd(&g_refcnt2, 1);
                g_reflist2[s] = token;
            } else if (v2 - v1 < EPS_GAP) {
                int s = atomicAdd(&g_refcnt, 1);
                g_reftok[s] = token; g_pa[s] = j1; g_pb[s] = j2;
            }
        }
    }
}

// ---------------------------------------------------------------------------
// Kernel 3b: pairwise exact refine — one warp per flagged token, exact fp32
// distances to the two candidates only.
// ---------------------------------------------------------------------------
__global__ void k_refpair(const float* __restrict__ emb) {
    int lane = threadIdx.x & 31;
    int wg   = blockIdx.x * (blockDim.x >> 5) + (threadIdx.x >> 5);
    int nwp  = gridDim.x * (blockDim.x >> 5);
    int cnt  = g_refcnt;
    for (int j = wg; j < cnt; j += nwp) {
        int t = g_reftok[j], a = g_pa[j], b = g_pb[j];
        const float* zp = g_ze + (size_t)t * C_;
        float z0 = zp[lane], z1 = zp[lane + 32];
        const float* ea = emb + (size_t)a * C_;
        const float* eb = emb + (size_t)b * C_;
        float pa = z0 * ea[lane] + z1 * ea[lane + 32];
        float pb = z0 * eb[lane] + z1 * eb[lane + 32];
#pragma unroll
        for (int off = 16; off > 0; off >>= 1) {
            pa += __shfl_down_sync(0xffffffffu, pa, off);
            pb += __shfl_down_sync(0xffffffffu, pb, off);
        }
        if (lane == 0) {
            float da = g_en2[a] - 2.f * pa;
            float db = g_en2[b] - 2.f * pb;
            g_idx[t] = (db < da || (db == da && b < a)) ? b : a;
        }
    }
}

// ---------------------------------------------------------------------------
// Kernel 3c: full-scan exact refine for ultra-rare 3-way-tie tokens
// (expected empty; batch 4 tokens to keep registers low)
// ---------------------------------------------------------------------------
__global__ void k_reffull(const float* __restrict__ emb) {
    __shared__ float xs[4][64];
    __shared__ float rv[256];
    __shared__ int   ri[256];
    int tid = threadIdx.x;
    int cnt = g_refcnt2;
    if (cnt == 0) return;
    int nb = (cnt + 3) >> 2;
    for (int b = blockIdx.x; b < nb; b += gridDim.x) {
        int base = b * 4;
        int nt = min(4, cnt - base);
        __syncthreads();
        for (int f = tid; f < 256; f += 256) {
            int t = f >> 6, c = f & 63;
            xs[t][c] = (t < nt) ? g_ze[(size_t)g_reflist2[base + t] * 64 + c] : 0.f;
        }
        __syncthreads();

        float best[4]; int bi[4];
#pragma unroll
        for (int t = 0; t < 4; t++) { best[t] = 3.4e38f; bi[t] = 0; }

        for (int k = tid; k < K_; k += 256) {
            float dot[4];
#pragma unroll
            for (int t = 0; t < 4; t++) dot[t] = 0.f;
            const float4* ep = (const float4*)(emb + (size_t)k * 64);
#pragma unroll
            for (int cc = 0; cc < 16; cc++) {
                float4 ev = ep[cc];
#pragma unroll
                for (int t = 0; t < 4; t++) {
                    dot[t] += ev.x * xs[t][4 * cc + 0] + ev.y * xs[t][4 * cc + 1]
                            + ev.z * xs[t][4 * cc + 2] + ev.w * xs[t][4 * cc + 3];
                }
            }
            float en = g_en2[k];
#pragma unroll
            for (int t = 0; t < 4; t++) {
                float dd = en - 2.f * dot[t];
                if (dd < best[t]) { best[t] = dd; bi[t] = k; }
            }
        }
        for (int t = 0; t < nt; t++) {
            rv[tid] = best[t]; ri[tid] = bi[t];
            __syncthreads();
            for (int s = 128; s > 0; s >>= 1) {
                if (tid < s) {
                    bool tk = (rv[tid + s] < rv[tid]) ||
                              (rv[tid + s] == rv[tid] && ri[tid + s] < ri[tid]);
                    if (tk) { rv[tid] = rv[tid + s]; ri[tid] = ri[tid + s]; }
                }
                __syncthreads();
            }
            if (tid == 0) g_idx[g_reflist2[base + t]] = ri[0];
            __syncthreads();
        }
    }
}

// ---------------------------------------------------------------------------
// Kernel 4: gather + loss partials + post-conv
// ---------------------------------------------------------------------------
__global__ void k_out(const float* __restrict__ emb,
                      const float* __restrict__ w,
                      const float* __restrict__ bias,
                      float* __restrict__ out) {
    __shared__ float ws[C_ * C_];
    __shared__ float bs[C_];
    __shared__ float red[128];
    int tid = threadIdx.x;
    for (int i = tid; i < C_ * C_ / 4; i += blockDim.x)
        ((float4*)ws)[i] = ((const float4*)w)[i];
    if (tid < C_) bs[tid] = bias[tid];
    __syncthreads();

    int n   = blockIdx.x * blockDim.x + tid;
    int idx = g_idx[n];

    float q[C_];
    const float4* ep = (const float4*)(emb + (size_t)idx * C_);
#pragma unroll
    for (int i = 0; i < 16; i++) ((float4*)q)[i] = ep[i];

    const float4* zep = (const float4*)(g_ze + (size_t)n * C_);
    float ls = 0.f;
#pragma unroll
    for (int i = 0; i < 16; i++) {
        float4 zv = zep[i];
        float d0 = zv.x - q[4 * i + 0];
        float d1 = zv.y - q[4 * i + 1];
        float d2 = zv.z - q[4 * i + 2];
        float d3 = zv.w - q[4 * i + 3];
        ls += d0 * d0 + d1 * d1 + d2 * d2 + d3 * d3;
    }

    int b   = n >> 12;
    int pos = n & 4095;
    float* op = out + (size_t)b * CHW_ + pos;
#pragma unroll 4
    for (int o = 0; o < C_; o++) {
        float acc = bs[o];
#pragma unroll
        for (int c = 0; c < C_; c++) acc += ws[o * C_ + c] * q[c];
        op[(size_t)o * HW_] = acc;
    }

    red[tid] = ls;
    __syncthreads();
    for (int s = 64; s > 0; s >>= 1) {
        if (tid < s) red[tid] += red[tid + s];
        __syncthreads();
    }
    if (tid == 0) g_losspart[blockIdx.x] = red[0];
}

__global__ void k_loss(float* __restrict__ out_loss) {
    if (threadIdx.x == 0) {
        double s = 0.0;
        for (int i = 0; i < 256; i++) s += (double)g_losspart[i];
        *out_loss = (float)(1.25 * s / (double)OUT_ELEMS);
    }
}

// ---------------------------------------------------------------------------
extern "C" void kernel_launch(void* const* d_in, const int* in_sizes, int n_in,
                              void* d_out, int out_size) {
    const float* z      = (const float*)d_in[0];
    const float* pre_w  = (const float*)d_in[1];
    const float* pre_b  = (const float*)d_in[2];
    const float* emb    = (const float*)d_in[3];
    const float* post_w = (const float*)d_in[4];
    const float* post_b = (const float*)d_in[5];
    float* out = (float*)d_out;

    cudaFuncSetAttribute(k_argmin_mma, cudaFuncAttributeMaxDynamicSharedMemorySize, SMEM_TC);

    k_pre      <<<N_ / 128, 128>>>(z, pre_w, pre_b);
    k_embcvt   <<<K_ / 128, 128>>>(emb);
    k_argmin_mma<<<N_ / 128, 256, SMEM_TC>>>();
    k_refpair  <<<64, 256>>>(emb);
    k_reffull  <<<32, 256>>>(emb);
    k_out      <<<N_ / 128, 128>>>(emb, post_w, post_b, out);
    k_loss     <<<1, 32>>>(out + (out_size - 1));
}

// round 17
// speedup vs baseline: 1.0096x; 1.0096x over previous
#include <cuda_runtime.h>
#include <cuda_fp16.h>
#include <cstdint>

#define B_   8
#define C_   64
#define HW_  4096
#define N_   32768
#define K_   8192
#define CHW_ (C_*HW_)
#define OUT_ELEMS (B_*C_*HW_)
#define EPS_GAP 5.0e-4f

__device__ float  g_ze[N_ * C_];
__device__ __half g_ah[N_ * C_], g_al[N_ * C_];   // fp16 splits of -2*ze
__device__ __half g_eh[K_ * C_], g_el[K_ * C_];   // fp16 splits of emb
__device__ float  g_en2[K_];
__device__ int    g_idx[N_];
__device__ int    g_refcnt;      // pairwise-refine count
__device__ int    g_refcnt2;     // full-scan refine count (expected ~0)
__device__ int    g_reftok[N_], g_pa[N_], g_pb[N_];
__device__ int    g_reflist2[N_];
__device__ float  g_losspart[256];

// ---------------------------------------------------------------------------
// PTX helpers (sm_80-era: compile cleanly for compute_103)
// ---------------------------------------------------------------------------
__device__ __forceinline__ uint32_t smem_u32(const void* p) {
    uint32_t a;
    asm("{ .reg .u64 t; cvta.to.shared.u64 t, %1; cvt.u32.u64 %0, t; }" : "=r"(a) : "l"(p));
    return a;
}
__device__ __forceinline__ void cpasync16(uint32_t s, const void* g) {
    asm volatile("cp.async.cg.shared.global [%0], [%1], 16;" :: "r"(s), "l"(g));
}
#define CP_COMMIT() asm volatile("cp.async.commit_group;" ::: "memory")
#define CP_WAIT1()  asm volatile("cp.async.wait_group 1;" ::: "memory")
#define CP_WAIT0()  asm volatile("cp.async.wait_group 0;" ::: "memory")

__device__ __forceinline__ void ldsm4(uint32_t* r, uint32_t addr) {
    asm volatile("ldmatrix.sync.aligned.m8n8.x4.shared.b16 {%0,%1,%2,%3}, [%4];"
                 : "=r"(r[0]), "=r"(r[1]), "=r"(r[2]), "=r"(r[3]) : "r"(addr));
}
__device__ __forceinline__ void mma16816(float* d, const uint32_t* a, uint32_t b0, uint32_t b1) {
    asm volatile("mma.sync.aligned.m16n8k16.row.col.f32.f16.f16.f32 "
                 "{%0,%1,%2,%3}, {%4,%5,%6,%7}, {%8,%9}, {%0,%1,%2,%3};"
                 : "+f"(d[0]), "+f"(d[1]), "+f"(d[2]), "+f"(d[3])
                 : "r"(a[0]), "r"(a[1]), "r"(a[2]), "r"(a[3]), "r"(b0), "r"(b1));
}

// ---------------------------------------------------------------------------
// Kernel 1: pre-conv + 2-way fp16 split of (-2*ze)
// ---------------------------------------------------------------------------
__global__ void k_pre(const float* __restrict__ z,
                      const float* __restrict__ w,
                      const float* __restrict__ bias) {
    __shared__ float ws[C_ * C_];
    __shared__ float bs[C_];
    int tid = threadIdx.x;
    for (int i = tid; i < C_ * C_ / 4; i += blockDim.x)
        ((float4*)ws)[i] = ((const float4*)w)[i];
    if (tid < C_) bs[tid] = bias[tid];
    __syncthreads();

    int n   = blockIdx.x * blockDim.x + tid;
    int b   = n >> 12;
    int pos = n & 4095;
    const float* zp = z + (size_t)b * CHW_ + pos;

    float zr[C_];
#pragma unroll
    for (int c = 0; c < C_; c++) zr[c] = zp[(size_t)c * HW_];

    float*  zeout = g_ze + (size_t)n * C_;
    __half* ahp   = g_ah + (size_t)n * C_;
    __half* alp   = g_al + (size_t)n * C_;

    for (int og = 0; og < C_; og += 8) {
        float zeb[8];
        __half hb[8], lb[8];
#pragma unroll
        for (int oo = 0; oo < 8; oo++) {
            int o = og + oo;
            float acc = bs[o];
#pragma unroll
            for (int c = 0; c < C_; c++) acc += ws[o * C_ + c] * zr[c];
            zeb[oo] = acc;
            float x = -2.f * acc;
            __half h = __float2half_rn(x);
            float r = x - __half2float(h);
            hb[oo] = h; lb[oo] = __float2half_rn(r);
        }
        *(uint4*)(zeout + og)     = ((uint4*)zeb)[0];
        *(uint4*)(zeout + og + 4) = ((uint4*)zeb)[1];
        *(uint4*)(ahp + og) = *(uint4*)hb;
        *(uint4*)(alp + og) = *(uint4*)lb;
    }
}

// ---------------------------------------------------------------------------
// Kernel 2: codebook 2-way fp16 split + row norms (+ counter resets)
// ---------------------------------------------------------------------------
__global__ void k_embcvt(const float* __restrict__ emb) {
    if (blockIdx.x == 0 && threadIdx.x == 0) { g_refcnt = 0; g_refcnt2 = 0; }
    int k = blockIdx.x * blockDim.x + threadIdx.x;
    const float* e = emb + (size_t)k * C_;
    __half* hp = g_eh + (size_t)k * C_;
    __half* lp = g_el + (size_t)k * C_;
    float s = 0.f;
    for (int og = 0; og < C_; og += 8) {
        float v[8];
        ((float4*)v)[0] = *(const float4*)(e + og);
        ((float4*)v)[1] = *(const float4*)(e + og + 4);
        __half hb[8], lb[8];
#pragma unroll
        for (int i = 0; i < 8; i++) {
            float x = v[i];
            s += x * x;
            __half h = __float2half_rn(x);
            hb[i] = h; lb[i] = __float2half_rn(x - __half2float(h));
        }
        *(uint4*)(hp + og) = *(uint4*)hb;
        *(uint4*)(lp + og) = *(uint4*)lb;
    }
    g_en2[k] = s;
}

// ---------------------------------------------------------------------------
// Kernel 3: HMMA argmin (fp16 splits, top-3 tracking).
// d = ah*eh + al*eh + ah*el (fp32 accum) ~ -2 z.e  (rigorous err <~1.2e-4).
// Epilogue: s = d + en2; per-token best1/2/3; gap2<EPS -> pair refine,
// gap3<EPS -> full refine.
// ---------------------------------------------------------------------------
#define NC        128
#define NCHUNK    (K_ / NC)      // 64
#define SM_AH     0
#define SM_AL     16384
#define SM_B      32768
#define BUFSTRIDE 33280          // eh 16384 + el 16384 + en2 512
#define SMEM_TC   (SM_B + 2 * BUFSTRIDE)   // 99328

__device__ __forceinline__ void load_chunk(uint32_t sb, int buf, int kc, int tid) {
    uint32_t dst = sb + SM_B + buf * BUFSTRIDE;
#pragma unroll
    for (int i = 0; i < 4; i++) {
        int f = tid + i * 256;
        int row = f >> 3, c = f & 7;
        uint32_t off = row * 128 + ((c ^ (row & 7)) * 16);
        size_t src = (size_t)(kc + row) * 128 + c * 16;
        cpasync16(dst + off,         (const char*)g_eh + src);
        cpasync16(dst + 16384 + off, (const char*)g_el + src);
    }
    if (tid < 32)
        cpasync16(dst + 32768 + tid * 16, (const char*)g_en2 + (size_t)kc * 4 + tid * 16);
}

__global__ void __launch_bounds__(256, 2) k_argmin_mma() {
    extern __shared__ char smem[];
    uint32_t sb = smem_u32(smem);
    int tid  = threadIdx.x;
    int w    = tid >> 5;
    int lane = tid & 31;
    int t0   = blockIdx.x * 128;

    // prologue: A tiles + chunk0, chunk1
#pragma unroll
    for (int i = 0; i < 4; i++) {
        int f = tid + i * 256;
        int row = f >> 3, c = f & 7;
        uint32_t off = row * 128 + ((c ^ (row & 7)) * 16);
        size_t src = (size_t)(t0 + row) * 128 + c * 16;
        cpasync16(sb + SM_AH + off, (const char*)g_ah + src);
        cpasync16(sb + SM_AL + off, (const char*)g_al + src);
    }
    load_chunk(sb, 0, 0, tid);
    CP_COMMIT();
    load_chunk(sb, 1, NC, tid);
    CP_COMMIT();

    uint32_t aH[4][4], aL[4][4];
    float b1v[2] = {3.4e38f, 3.4e38f}, b2v[2] = {3.4e38f, 3.4e38f},
          b3v[2] = {3.4e38f, 3.4e38f};
    int   i1v[2] = {0, 0}, i2v[2] = {0, 0};

    for (int c = 0; c < NCHUNK; c++) {
        if (c < NCHUNK - 1) { CP_WAIT1(); } else { CP_WAIT0(); }
        __syncthreads();
        if (c == 0) {
            int quad = lane >> 3, rin = lane & 7;
            int arow = 16 * w + (quad & 1) * 8 + rin;
#pragma unroll
            for (int kk = 0; kk < 4; kk++) {
                uint32_t cidx = kk * 2 + (quad >> 1);
                uint32_t off  = arow * 128 + (((cidx ^ rin) & 7) * 16);
                ldsm4(aH[kk], sb + SM_AH + off);
                ldsm4(aL[kk], sb + SM_AL + off);
            }
        }
        uint32_t bbase = sb + SM_B + (c & 1) * BUFSTRIDE;
        const float* en2c = (const float*)(smem + SM_B + (c & 1) * BUFSTRIDE + 32768);
        int kc = c * NC;
        int m = lane >> 3, rin = lane & 7;

#pragma unroll 2
        for (int nt = 0; nt < 16; nt++) {
            int brow = nt * 8 + rin;
            float d[4] = {0.f, 0.f, 0.f, 0.f};
#pragma unroll
            for (int g = 0; g < 2; g++) {
                uint32_t eh4[4], el4[4];
                uint32_t off = brow * 128 + ((((g * 4 + m) ^ rin) & 7) * 16);
                ldsm4(eh4, bbase + off);
                ldsm4(el4, bbase + 16384 + off);
                mma16816(d, aH[2 * g],     eh4[0], eh4[1]);
                mma16816(d, aH[2 * g + 1], eh4[2], eh4[3]);
                mma16816(d, aL[2 * g],     eh4[0], eh4[1]);
                mma16816(d, aL[2 * g + 1], eh4[2], eh4[3]);
                mma16816(d, aH[2 * g],     el4[0], el4[1]);
                mma16816(d, aH[2 * g + 1], el4[2], el4[3]);
            }
            int col0 = nt * 8 + 2 * (lane & 3);
            float e0 = en2c[col0], e1 = en2c[col0 + 1];
            float s01[2][2] = { { d[0] + e0, d[1] + e1 },
                                { d[2] + e0, d[3] + e1 } };
            int gc0 = kc + col0;
#pragma unroll
            for (int h = 0; h < 2; h++) {
#pragma unroll
                for (int jj = 0; jj < 2; jj++) {
                    float s = s01[h][jj];
                    int   gk = gc0 + jj;
                    if (s < b3v[h]) {
                        if (s < b2v[h]) {
                            b3v[h] = b2v[h];
                            if (s < b1v[h]) {
                                b2v[h] = b1v[h]; i2v[h] = i1v[h];
                                b1v[h] = s;      i1v[h] = gk;
                            } else { b2v[h] = s; i2v[h] = gk; }
                        } else b3v[h] = s;
                    }
                }
            }
        }
        __syncthreads();
        if (c + 2 < NCHUNK) { load_chunk(sb, c & 1, (c + 2) * NC, tid); CP_COMMIT(); }
    }

    // quad reduce: merge sorted top-3 triples across 4 lanes
#pragma unroll
    for (int h = 0; h < 2; h++) {
        float v1 = b1v[h], v2 = b2v[h], v3 = b3v[h];
        int   j1 = i1v[h], j2 = i2v[h];
#pragma unroll
        for (int off = 2; off > 0; off >>= 1) {
            float c1 = __shfl_down_sync(0xffffffffu, v1, off, 4);
            float c2 = __shfl_down_sync(0xffffffffu, v2, off, 4);
            float c3 = __shfl_down_sync(0xffffffffu, v3, off, 4);
            int   k1 = __shfl_down_sync(0xffffffffu, j1, off, 4);
            int   k2 = __shfl_down_sync(0xffffffffu, j2, off, 4);
            bool sw = (c1 < v1) || (c1 == v1 && k1 < j1);
            if (sw) {
                float tv; int ti;
                tv = v1; v1 = c1; c1 = tv;  ti = j1; j1 = k1; k1 = ti;
                tv = v2; v2 = c2; c2 = tv;  ti = j2; j2 = k2; k2 = ti;
                tv = v3; v3 = c3; c3 = tv;
            }
            // v1 is champion; merge remainder
            bool t2 = (c1 < v2) || (c1 == v2 && k1 < j2);
            float n3;
            if (t2) { n3 = fminf(v2, c2); v2 = c1; j2 = k1; }
            else    { n3 = fminf(v3, c1); }
            v3 = n3;
        }
        if ((lane & 3) == 0) {
            int token = t0 + w * 16 + (lane >> 2) + h * 8;
            g_idx[token] = j1;
            if (v3 - v1 < EPS_GAP) {
                int s = atomicAdd(&g_refcnt2, 1);
                g_reflist2[s] = token;
            } else if (v2 - v1 < EPS_GAP) {
                int s = atomicAdd(&g_refcnt, 1);
                g_reftok[s] = token; g_pa[s] = j1; g_pb[s] = j2;
            }
        }
    }
}

// ---------------------------------------------------------------------------
// Kernel 3b: pairwise exact refine — one warp per flagged token, exact fp32
// distances to the two candidates only.
// ---------------------------------------------------------------------------
__global__ void k_refpair(const float* __restrict__ emb) {
    int lane = threadIdx.x & 31;
    int wg   = blockIdx.x * (blockDim.x >> 5) + (threadIdx.x >> 5);
    int nwp  = gridDim.x * (blockDim.x >> 5);
    int cnt  = g_refcnt;
    for (int j = wg; j < cnt; j += nwp) {
        int t = g_reftok[j], a = g_pa[j], b = g_pb[j];
        const float* zp = g_ze + (size_t)t * C_;
        float z0 = zp[lane], z1 = zp[lane + 32];
        const float* ea = emb + (size_t)a * C_;
        const float* eb = emb + (size_t)b * C_;
        float pa = z0 * ea[lane] + z1 * ea[lane + 32];
        float pb = z0 * eb[lane] + z1 * eb[lane + 32];
#pragma unroll
        for (int off = 16; off > 0; off >>= 1) {
            pa += __shfl_down_sync(0xffffffffu, pa, off);
            pb += __shfl_down_sync(0xffffffffu, pb, off);
        }
        if (lane == 0) {
            float da = g_en2[a] - 2.f * pa;
            float db = g_en2[b] - 2.f * pb;
            g_idx[t] = (db < da || (db == da && b < a)) ? b : a;
        }
    }
}

// ---------------------------------------------------------------------------
// Kernel 3c: full-scan exact refine for ultra-rare 3-way-tie tokens
// (expected empty; batch 4 tokens to keep registers low)
// ---------------------------------------------------------------------------
__global__ void k_reffull(const float* __restrict__ emb) {
    __shared__ float xs[4][64];
    __shared__ float rv[256];
    __shared__ int   ri[256];
    int tid = threadIdx.x;
    int cnt = g_refcnt2;
    if (cnt == 0) return;
    int nb = (cnt + 3) >> 2;
    for (int b = blockIdx.x; b < nb; b += gridDim.x) {
        int base = b * 4;
        int nt = min(4, cnt - base);
        __syncthreads();
        for (int f = tid; f < 256; f += 256) {
            int t = f >> 6, c = f & 63;
            xs[t][c] = (t < nt) ? g_ze[(size_t)g_reflist2[base + t] * 64 + c] : 0.f;
        }
        __syncthreads();

        float best[4]; int bi[4];
#pragma unroll
        for (int t = 0; t < 4; t++) { best[t] = 3.4e38f; bi[t] = 0; }

        for (int k = tid; k < K_; k += 256) {
            float dot[4];
#pragma unroll
            for (int t = 0; t < 4; t++) dot[t] = 0.f;
            const float4* ep = (const float4*)(emb + (size_t)k * 64);
#pragma unroll
            for (int cc = 0; cc < 16; cc++) {
                float4 ev = ep[cc];
#pragma unroll
                for (int t = 0; t < 4; t++) {
                    dot[t] += ev.x * xs[t][4 * cc + 0] + ev.y * xs[t][4 * cc + 1]
                            + ev.z * xs[t][4 * cc + 2] + ev.w * xs[t][4 * cc + 3];
                }
            }
            float en = g_en2[k];
#pragma unroll
            for (int t = 0; t < 4; t++) {
                float dd = en - 2.f * dot[t];
                if (dd < best[t]) { best[t] = dd; bi[t] = k; }
            }
        }
        for (int t = 0; t < nt; t++) {
            rv[tid] = best[t]; ri[tid] = bi[t];
            __syncthreads();
            for (int s = 128; s > 0; s >>= 1) {
                if (tid < s) {
                    bool tk = (rv[tid + s] < rv[tid]) ||
                              (rv[tid + s] == rv[tid] && ri[tid + s] < ri[tid]);
                    if (tk) { rv[tid] = rv[tid + s]; ri[tid] = ri[tid + s]; }
                }
                __syncthreads();
            }
            if (tid == 0) g_idx[g_reflist2[base + t]] = ri[0];
            __syncthreads();
        }
    }
}

// ---------------------------------------------------------------------------
// Kernel 4: gather + loss partials + post-conv
// ---------------------------------------------------------------------------
__global__ void k_out(const float* __restrict__ emb,
                      const float* __restrict__ w,
                      const float* __restrict__ bias,
                      float* __restrict__ out) {
    __shared__ float ws[C_ * C_];
    __shared__ float bs[C_];
    __shared__ float red[128];
    int tid = threadIdx.x;
    for (int i = tid; i < C_ * C_ / 4; i += blockDim.x)
        ((float4*)ws)[i] = ((const float4*)w)[i];
    if (tid < C_) bs[tid] = bias[tid];
    __syncthreads();

    int n   = blockIdx.x * blockDim.x + tid;
    int idx = g_idx[n];

    float q[C_];
    const float4* ep = (const float4*)(emb + (size_t)idx * C_);
#pragma unroll
    for (int i = 0; i < 16; i++) ((float4*)q)[i] = ep[i];

    const float4* zep = (const float4*)(g_ze + (size_t)n * C_);
    float ls = 0.f;
#pragma unroll
    for (int i = 0; i < 16; i++) {
        float4 zv = zep[i];
        float d0 = zv.x - q[4 * i + 0];
        float d1 = zv.y - q[4 * i + 1];
        float d2 = zv.z - q[4 * i + 2];
        float d3 = zv.w - q[4 * i + 3];
        ls += d0 * d0 + d1 * d1 + d2 * d2 + d3 * d3;
    }

    int b   = n >> 12;
    int pos = n & 4095;
    float* op = out + (size_t)b * CHW_ + pos;
#pragma unroll 4
    for (int o = 0; o < C_; o++) {
        float acc = bs[o];
#pragma unroll
        for (int c = 0; c < C_; c++) acc += ws[o * C_ + c] * q[c];
        op[(size_t)o * HW_] = acc;
    }

    red[tid] = ls;
    __syncthreads();
    for (int s = 64; s > 0; s >>= 1) {
        if (tid < s) red[tid] += red[tid + s];
        __syncthreads();
    }
    if (tid == 0) g_losspart[blockIdx.x] = red[0];
}

__global__ void k_loss(float* __restrict__ out_loss) {
    if (threadIdx.x == 0) {
        double s = 0.0;
        for (int i = 0; i < 256; i++) s += (double)g_losspart[i];
        *out_loss = (float)(1.25 * s / (double)OUT_ELEMS);
    }
}

// ---------------------------------------------------------------------------
extern "C" void kernel_launch(void* const* d_in, const int* in_sizes, int n_in,
                              void* d_out, int out_size) {
    const float* z      = (const float*)d_in[0];
    const float* pre_w  = (const float*)d_in[1];
    const float* pre_b  = (const float*)d_in[2];
    const float* emb    = (const float*)d_in[3];
    const float* post_w = (const float*)d_in[4];
    const float* post_b = (const float*)d_in[5];
    float* out = (float*)d_out;

    cudaFuncSetAttribute(k_argmin_mma, cudaFuncAttributeMaxDynamicSharedMemorySize, SMEM_TC);

    k_pre      <<<N_ / 128, 128>>>(z, pre_w, pre_b);
    k_embcvt   <<<K_ / 128, 128>>>(emb);
    k_argmin_mma<<<N_ / 128, 256, SMEM_TC>>>();
    k_refpair  <<<64, 256>>>(emb);
    k_reffull  <<<32, 256>>>(emb);
    k_out      <<<N_ / 128, 128>>>(emb, post_w, post_b, out);
    k_loss     <<<1, 32>>>(out + (out_size - 1));
}